// round 6
// baseline (speedup 1.0000x reference)
#include <cuda_runtime.h>
#include <cuda_bf16.h>
#include <cstdint>
#include <cstddef>

// Problem constants
#define T_SEQ 2048
#define D_MODEL 3584
#define HQ 28
#define HKV 4
#define DH 128
#define QKV_N 4608          // (HQ + 2*HKV) * DH
#define K_OFF 3584          // HQ*DH
#define V_OFF 4096          // (HQ+HKV)*DH

// Scratch (allocation-free rule: __device__ globals)
__device__ float g_qkv[(size_t)T_SEQ * QKV_N];   // 37.7 MB
__device__ float g_attn[(size_t)T_SEQ * D_MODEL]; // 29.4 MB

// ---------------------------------------------------------------------------
// TF32 split helper: x = hi + lo, both representable in tf32.
// ---------------------------------------------------------------------------
__device__ __forceinline__ void split_tf32(float x, uint32_t& hi, uint32_t& lo)
{
    uint32_t h;
    asm("cvt.rna.tf32.f32 %0, %1;" : "=r"(h) : "f"(x));
    float hf = __uint_as_float(h);
    float lf = x - hf;                      // exact (Dekker split)
    uint32_t l;
    asm("cvt.rna.tf32.f32 %0, %1;" : "=r"(l) : "f"(lf));
    hi = h;
    lo = l;
}

__device__ __forceinline__ void mma_tf32(float* c, const uint32_t* a, const uint32_t* b)
{
    asm volatile(
        "mma.sync.aligned.m16n8k8.row.col.f32.tf32.tf32.f32 "
        "{%0,%1,%2,%3}, {%4,%5,%6,%7}, {%8,%9}, {%0,%1,%2,%3};"
        : "+f"(c[0]), "+f"(c[1]), "+f"(c[2]), "+f"(c[3])
        : "r"(a[0]), "r"(a[1]), "r"(a[2]), "r"(a[3]), "r"(b[0]), "r"(b[1]));
}

// ---------------------------------------------------------------------------
// 3xTF32 GEMM: C[M,N] = A[M,K] @ B[K,N] (+bias), fp32-class accuracy.
// BM=BN=128, BK=16, 256 threads = 8 warps (2 x 4), warp tile 64x32.
// Each warp: 4x4 grid of m16n8k8 mma tiles; 3 MMAs per tile (hh, hl, lh).
// Smem stride 136 (mod 32 == 8) -> conflict-free fragment loads.
// ---------------------------------------------------------------------------
#define GPAD 136

__global__ __launch_bounds__(256) void tf32_gemm_kernel(
    const float* __restrict__ A, const float* __restrict__ B,
    const float* __restrict__ bias, float* __restrict__ C,
    int M, int N, int K)
{
    __shared__ uint32_t Ah[16][GPAD];   // [k][m] hi
    __shared__ uint32_t Al[16][GPAD];   // [k][m] lo
    __shared__ uint32_t Bh[16][GPAD];   // [k][n] hi
    __shared__ uint32_t Bl[16][GPAD];   // [k][n] lo

    const int bx = blockIdx.x;          // N tile
    const int by = blockIdx.y;          // M tile
    const int tid = threadIdx.x;
    const int wid = tid >> 5;
    const int lane = tid & 31;
    const int warp_m = wid & 1;         // 0..1
    const int warp_n = wid >> 1;        // 0..3
    const int lr = lane >> 2;           // 0..7
    const int lc = lane & 3;            // 0..3

    // gmem load mapping
    const int a_row = tid >> 1;             // 0..127
    const int a_col = (tid & 1) * 8;        // 0 or 8
    const int b_row = tid >> 4;             // 0..15
    const int b_col = (tid & 15) * 8;       // 0..120

    const float* Ap = A + (size_t)(by * 128 + a_row) * K + a_col;
    const float* Bp = B + (size_t)b_row * N + bx * 128 + b_col;

    float acc[4][4][4];
#pragma unroll
    for (int i = 0; i < 4; ++i)
#pragma unroll
        for (int j = 0; j < 4; ++j)
#pragma unroll
            for (int r = 0; r < 4; ++r) acc[i][j][r] = 0.f;

    for (int k0 = 0; k0 < K; k0 += 16) {
        // ---- load + split A (128x16) transposed into [k][m]
        {
            float4 v0 = *(const float4*)(Ap + k0);
            float4 v1 = *(const float4*)(Ap + k0 + 4);
            float av[8] = {v0.x, v0.y, v0.z, v0.w, v1.x, v1.y, v1.z, v1.w};
#pragma unroll
            for (int i = 0; i < 8; ++i) {
                uint32_t h, l;
                split_tf32(av[i], h, l);
                Ah[a_col + i][a_row] = h;
                Al[a_col + i][a_row] = l;
            }
        }
        // ---- load + split B (16x128) into [k][n]
        {
            float4 v0 = *(const float4*)(Bp + (size_t)k0 * N);
            float4 v1 = *(const float4*)(Bp + (size_t)k0 * N + 4);
            float bv[8] = {v0.x, v0.y, v0.z, v0.w, v1.x, v1.y, v1.z, v1.w};
#pragma unroll
            for (int i = 0; i < 8; ++i) {
                uint32_t h, l;
                split_tf32(bv[i], h, l);
                Bh[b_row][b_col + i] = h;
                Bl[b_row][b_col + i] = l;
            }
        }
        __syncthreads();

#pragma unroll
        for (int ks = 0; ks < 16; ks += 8) {
            // A fragments: 4 m-tiles, hi+lo
            uint32_t ah[4][4], al[4][4];
#pragma unroll
            for (int mt = 0; mt < 4; ++mt) {
                int m0 = warp_m * 64 + mt * 16;
                ah[mt][0] = Ah[ks + lc][m0 + lr];
                ah[mt][1] = Ah[ks + lc][m0 + lr + 8];
                ah[mt][2] = Ah[ks + lc + 4][m0 + lr];
                ah[mt][3] = Ah[ks + lc + 4][m0 + lr + 8];
                al[mt][0] = Al[ks + lc][m0 + lr];
                al[mt][1] = Al[ks + lc][m0 + lr + 8];
                al[mt][2] = Al[ks + lc + 4][m0 + lr];
                al[mt][3] = Al[ks + lc + 4][m0 + lr + 8];
            }
            // B fragments: 4 n-tiles, hi+lo
            uint32_t bh[4][2], bl[4][2];
#pragma unroll
            for (int nt = 0; nt < 4; ++nt) {
                int n0 = warp_n * 32 + nt * 8;
                bh[nt][0] = Bh[ks + lc][n0 + lr];
                bh[nt][1] = Bh[ks + lc + 4][n0 + lr];
                bl[nt][0] = Bl[ks + lc][n0 + lr];
                bl[nt][1] = Bl[ks + lc + 4][n0 + lr];
            }
#pragma unroll
            for (int mt = 0; mt < 4; ++mt)
#pragma unroll
                for (int nt = 0; nt < 4; ++nt) {
                    mma_tf32(acc[mt][nt], ah[mt], bl[nt]);   // hi*lo
                    mma_tf32(acc[mt][nt], al[mt], bh[nt]);   // lo*hi
                    mma_tf32(acc[mt][nt], ah[mt], bh[nt]);   // hi*hi
                }
        }
        __syncthreads();
    }

    // ---- epilogue
#pragma unroll
    for (int mt = 0; mt < 4; ++mt) {
        int row = by * 128 + warp_m * 64 + mt * 16 + lr;
#pragma unroll
        for (int nt = 0; nt < 4; ++nt) {
            int col = bx * 128 + warp_n * 32 + nt * 8 + lc * 2;
            float bv0 = 0.f, bv1 = 0.f;
            if (bias) { bv0 = bias[col]; bv1 = bias[col + 1]; }
            float2 r0 = make_float2(acc[mt][nt][0] + bv0, acc[mt][nt][1] + bv1);
            float2 r1 = make_float2(acc[mt][nt][2] + bv0, acc[mt][nt][3] + bv1);
            *(float2*)&C[(size_t)row * N + col] = r0;
            *(float2*)&C[(size_t)(row + 8) * N + col] = r1;
        }
    }
}

// ---------------------------------------------------------------------------
// RoPE: in-place on q (heads 0..27) and k (heads 28..31) of g_qkv.
// ---------------------------------------------------------------------------
__global__ __launch_bounds__(256) void rope_kernel(const int* __restrict__ pos,
                                                   float* __restrict__ qkv)
{
    int idx = blockIdx.x * 256 + threadIdx.x;   // T * 32 * 64 total
    int j = idx & 63;
    int h = (idx >> 6) & 31;
    int t = idx >> 11;
    if (t >= T_SEQ) return;

    float inv_freq = expf(-13.815510557964274f * (float)j * (1.0f / 64.0f));
    float ang = (float)pos[t] * inv_freq;
    float s, c;
    sincosf(ang, &s, &c);

    size_t base;
    if (h < HQ) base = (size_t)t * QKV_N + (size_t)h * DH;
    else        base = (size_t)t * QKV_N + K_OFF + (size_t)(h - HQ) * DH;

    float x1 = qkv[base + j];
    float x2 = qkv[base + 64 + j];
    qkv[base + j]      = x1 * c - x2 * s;
    qkv[base + 64 + j] = x2 * c + x1 * s;
}

// ---------------------------------------------------------------------------
// Flash attention, fp32, causal, GQA (group 7).  (unchanged from R5 baseline)
// ---------------------------------------------------------------------------
#define FBM 64
#define FBN 64
#define QS_PAD 68
#define FLASH_SMEM_FLOATS (128 * QS_PAD * 2 + FBN * DH + FBM * QS_PAD)
#define FLASH_SMEM_BYTES (FLASH_SMEM_FLOATS * 4)

__global__ __launch_bounds__(256) void flash_kernel(const float* __restrict__ qkv,
                                                    float* __restrict__ attn)
{
    extern __shared__ float sm[];
    float* Qs = sm;                       // [DH][QS_PAD] transposed
    float* Ks = Qs + 128 * QS_PAD;        // [DH][QS_PAD] transposed
    float* Vs = Ks + 128 * QS_PAD;        // [FBN][DH]
    float* Ps = Vs + FBN * DH;            // [FBM][QS_PAD]

    const int qt = blockIdx.x;
    const int h = blockIdx.y;
    const int hkv = h / 7;
    const int tid = threadIdx.x;
    const int tx = tid & 15;
    const int ty = tid >> 4;
    const float scale = 0.08838834764831845f;

    for (int idx = tid; idx < FBM * 32; idx += 256) {
        int m = idx >> 5;
        int k4 = (idx & 31) << 2;
        float4 v = *(const float4*)&qkv[(size_t)(qt * FBM + m) * QKV_N + h * DH + k4];
        Qs[(k4 + 0) * QS_PAD + m] = v.x;
        Qs[(k4 + 1) * QS_PAD + m] = v.y;
        Qs[(k4 + 2) * QS_PAD + m] = v.z;
        Qs[(k4 + 3) * QS_PAD + m] = v.w;
    }

    float o[4][8];
    float mrow[4], lrow[4];
#pragma unroll
    for (int i = 0; i < 4; ++i) {
        mrow[i] = -1e30f;
        lrow[i] = 0.f;
#pragma unroll
        for (int d = 0; d < 8; ++d) o[i][d] = 0.f;
    }

    for (int kt = 0; kt <= qt; ++kt) {
        __syncthreads();
        for (int idx = tid; idx < FBN * 32; idx += 256) {
            int r = idx >> 5;
            int k4 = (idx & 31) << 2;
            size_t base = (size_t)(kt * FBN + r) * QKV_N;
            float4 kv = *(const float4*)&qkv[base + K_OFF + hkv * DH + k4];
            Ks[(k4 + 0) * QS_PAD + r] = kv.x;
            Ks[(k4 + 1) * QS_PAD + r] = kv.y;
            Ks[(k4 + 2) * QS_PAD + r] = kv.z;
            Ks[(k4 + 3) * QS_PAD + r] = kv.w;
            float4 vv = *(const float4*)&qkv[base + V_OFF + hkv * DH + k4];
            *(float4*)&Vs[r * DH + k4] = vv;
        }
        __syncthreads();

        float s[4][4];
#pragma unroll
        for (int i = 0; i < 4; ++i)
#pragma unroll
            for (int j = 0; j < 4; ++j) s[i][j] = 0.f;

        for (int k = 0; k < DH; ++k) {
            float4 a = *(const float4*)&Qs[k * QS_PAD + 4 * ty];
            float4 b = *(const float4*)&Ks[k * QS_PAD + 4 * tx];
            float av[4] = {a.x, a.y, a.z, a.w};
            float bv[4] = {b.x, b.y, b.z, b.w};
#pragma unroll
            for (int i = 0; i < 4; ++i)
#pragma unroll
                for (int j = 0; j < 4; ++j)
                    s[i][j] += av[i] * bv[j];
        }

        const bool diag = (kt == qt);
#pragma unroll
        for (int i = 0; i < 4; ++i)
#pragma unroll
            for (int j = 0; j < 4; ++j) {
                float v = s[i][j] * scale;
                if (diag && (4 * tx + j) > (4 * ty + i)) v = -1e30f;
                s[i][j] = v;
            }

#pragma unroll
        for (int i = 0; i < 4; ++i) {
            float mx = fmaxf(fmaxf(s[i][0], s[i][1]), fmaxf(s[i][2], s[i][3]));
#pragma unroll
            for (int off = 1; off < 16; off <<= 1)
                mx = fmaxf(mx, __shfl_xor_sync(0xffffffffu, mx, off));
            float mn = fmaxf(mrow[i], mx);
            float corr = __expf(mrow[i] - mn);
            mrow[i] = mn;
            float rs = 0.f;
#pragma unroll
            for (int j = 0; j < 4; ++j) {
                float p = __expf(s[i][j] - mn);
                s[i][j] = p;
                rs += p;
            }
#pragma unroll
            for (int off = 1; off < 16; off <<= 1)
                rs += __shfl_xor_sync(0xffffffffu, rs, off);
            lrow[i] = lrow[i] * corr + rs;
#pragma unroll
            for (int d = 0; d < 8; ++d) o[i][d] *= corr;
            *(float4*)&Ps[(4 * ty + i) * QS_PAD + 4 * tx] =
                make_float4(s[i][0], s[i][1], s[i][2], s[i][3]);
        }
        __syncthreads();

        for (int kp = 0; kp < FBN; ++kp) {
            float4 v0 = *(const float4*)&Vs[kp * DH + tx * 8];
            float4 v1 = *(const float4*)&Vs[kp * DH + tx * 8 + 4];
#pragma unroll
            for (int i = 0; i < 4; ++i) {
                float p = Ps[(4 * ty + i) * QS_PAD + kp];
                o[i][0] += p * v0.x;
                o[i][1] += p * v0.y;
                o[i][2] += p * v0.z;
                o[i][3] += p * v0.w;
                o[i][4] += p * v1.x;
                o[i][5] += p * v1.y;
                o[i][6] += p * v1.z;
                o[i][7] += p * v1.w;
            }
        }
    }

#pragma unroll
    for (int i = 0; i < 4; ++i) {
        float inv = 1.f / lrow[i];
        int row = qt * FBM + 4 * ty + i;
        float* op = attn + (size_t)row * D_MODEL + h * DH + tx * 8;
        float4 r0 = make_float4(o[i][0] * inv, o[i][1] * inv, o[i][2] * inv, o[i][3] * inv);
        float4 r1 = make_float4(o[i][4] * inv, o[i][5] * inv, o[i][6] * inv, o[i][7] * inv);
        *(float4*)(op) = r0;
        *(float4*)(op + 4) = r1;
    }
}

// ---------------------------------------------------------------------------
extern "C" void kernel_launch(void* const* d_in, const int* in_sizes, int n_in,
                              void* d_out, int out_size)
{
    const int* positions   = (const int*)d_in[0];
    const float* hidden    = (const float*)d_in[1];
    const float* Wqkv      = (const float*)d_in[2];
    const float* bqkv      = (const float*)d_in[3];
    const float* Wo        = (const float*)d_in[4];
    float* out = (float*)d_out;

    float* qkv = nullptr;
    float* attn = nullptr;
    cudaGetSymbolAddress((void**)&qkv, g_qkv);
    cudaGetSymbolAddress((void**)&attn, g_attn);

    cudaFuncSetAttribute(flash_kernel,
                         cudaFuncAttributeMaxDynamicSharedMemorySize,
                         FLASH_SMEM_BYTES);

    // 1) QKV = hidden @ W_qkv + b   (3xTF32 tensor cores)
    tf32_gemm_kernel<<<dim3(QKV_N / 128, T_SEQ / 128), 256>>>(
        hidden, Wqkv, bqkv, qkv, T_SEQ, QKV_N, D_MODEL);

    // 2) RoPE on q and k heads
    rope_kernel<<<(T_SEQ * 32 * 64) / 256, 256>>>(positions, qkv);

    // 3) Causal GQA flash attention
    flash_kernel<<<dim3(T_SEQ / FBM, HQ), 256, FLASH_SMEM_BYTES>>>(qkv, attn);

    // 4) out = attn @ W_o   (3xTF32 tensor cores)
    tf32_gemm_kernel<<<dim3(D_MODEL / 128, T_SEQ / 128), 256>>>(
        attn, Wo, nullptr, out, T_SEQ, D_MODEL, D_MODEL);
}

// round 7
// speedup vs baseline: 1.2553x; 1.2553x over previous
#include <cuda_runtime.h>
#include <cuda_bf16.h>
#include <cstdint>
#include <cstddef>

// Problem constants
#define T_SEQ 2048
#define D_MODEL 3584
#define HQ 28
#define HKV 4
#define DH 128
#define QKV_N 4608
#define K_OFF 3584
#define V_OFF 4096

#define W_QKV_ELEMS ((size_t)D_MODEL * QKV_N)   // 16,515,072
#define W_O_ELEMS   ((size_t)D_MODEL * D_MODEL) // 12,845,056
#define HID_ELEMS   ((size_t)T_SEQ * D_MODEL)   // 7,340,032

// Scratch (__device__ globals per allocation-free rule)
__device__ float g_qkv[(size_t)T_SEQ * QKV_N];
__device__ float g_attn[HID_ELEMS];
__device__ uint32_t g_Wqkv_h[W_QKV_ELEMS];
__device__ uint32_t g_Wqkv_l[W_QKV_ELEMS];
__device__ uint32_t g_Wo_h[W_O_ELEMS];
__device__ uint32_t g_Wo_l[W_O_ELEMS];
__device__ uint32_t g_hid_h[HID_ELEMS];
__device__ uint32_t g_hid_l[HID_ELEMS];
__device__ uint32_t g_att_h[HID_ELEMS];
__device__ uint32_t g_att_l[HID_ELEMS];

// ---------------------------------------------------------------------------
// Split x = hi + lo (both tf32-representable), elementwise over gmem.
// ---------------------------------------------------------------------------
__device__ __forceinline__ void split1(float x, uint32_t& h, uint32_t& l)
{
    uint32_t hh;
    asm("cvt.rna.tf32.f32 %0, %1;" : "=r"(hh) : "f"(x));
    float lf = x - __uint_as_float(hh);
    uint32_t ll;
    asm("cvt.rna.tf32.f32 %0, %1;" : "=r"(ll) : "f"(lf));
    h = hh; l = ll;
}

__global__ __launch_bounds__(256) void split_kernel(
    const float* __restrict__ x, uint32_t* __restrict__ hi,
    uint32_t* __restrict__ lo, size_t n4)
{
    size_t i = (size_t)blockIdx.x * 256 + threadIdx.x;
    if (i >= n4) return;
    float4 v = *(const float4*)(x + i * 4);
    uint4 h, l;
    split1(v.x, h.x, l.x);
    split1(v.y, h.y, l.y);
    split1(v.z, h.z, l.z);
    split1(v.w, h.w, l.w);
    *(uint4*)(hi + i * 4) = h;
    *(uint4*)(lo + i * 4) = l;
}

// ---------------------------------------------------------------------------
// Pre-split 3xTF32 GEMM with 2-stage cp.async pipeline.
// C[M,N] = (Ah+Al)(Bh+Bl) ~= Ah*Bh + Ah*Bl + Al*Bh  (+bias)
// BM=BN=128, BK=16, 256 threads = 8 warps (2m x 4n), warp tile 64x32.
// ---------------------------------------------------------------------------
#define ASTRIDE 20            // u32 stride per A row (16 k + 4 pad)
#define BSTRIDE 136           // u32 stride per B row (128 n + 8 pad)
#define A_SZ (128 * ASTRIDE)  // 2560 u32 per A tile
#define B_SZ (16 * BSTRIDE)   // 2176 u32 per B tile
#define STAGE_U32 (2 * A_SZ + 2 * B_SZ)   // 9472 u32 = 37888 B
#define GEMM_SMEM_BYTES (2 * STAGE_U32 * 4)

__device__ __forceinline__ void cp16(uint32_t saddr, const void* g)
{
    asm volatile("cp.async.cg.shared.global [%0], [%1], 16;" :: "r"(saddr), "l"(g));
}

__device__ __forceinline__ void mma_tf32(float* c, const uint32_t* a, const uint32_t* b)
{
    asm volatile(
        "mma.sync.aligned.m16n8k8.row.col.f32.tf32.tf32.f32 "
        "{%0,%1,%2,%3}, {%4,%5,%6,%7}, {%8,%9}, {%0,%1,%2,%3};"
        : "+f"(c[0]), "+f"(c[1]), "+f"(c[2]), "+f"(c[3])
        : "r"(a[0]), "r"(a[1]), "r"(a[2]), "r"(a[3]), "r"(b[0]), "r"(b[1]));
}

__global__ __launch_bounds__(256, 2) void tf32s_gemm_kernel(
    const uint32_t* __restrict__ Ah, const uint32_t* __restrict__ Al,
    const uint32_t* __restrict__ Bh, const uint32_t* __restrict__ Bl,
    const float* __restrict__ bias, float* __restrict__ C,
    int M, int N, int K)
{
    extern __shared__ uint32_t smem_u[];

    const int bx = blockIdx.x;
    const int by = blockIdx.y;
    const int tid = threadIdx.x;
    const int wid = tid >> 5;
    const int lane = tid & 31;
    const int warp_m = wid & 1;
    const int warp_n = wid >> 1;
    const int lr = lane >> 2;   // 0..7
    const int lc = lane & 3;    // 0..3

    // cp.async chunk mapping (2 chunks of 16B per tile per thread)
    const int ac0 = tid * 2;

    float acc[4][4][4];
#pragma unroll
    for (int i = 0; i < 4; ++i)
#pragma unroll
        for (int j = 0; j < 4; ++j)
#pragma unroll
            for (int r = 0; r < 4; ++r) acc[i][j][r] = 0.f;

#define ISSUE(IT, STG) do {                                                       \
    int k0_ = (IT) * 16;                                                          \
    uint32_t sb_ = (uint32_t)__cvta_generic_to_shared(smem_u + (STG) * STAGE_U32);\
    _Pragma("unroll")                                                             \
    for (int q_ = 0; q_ < 2; ++q_) {                                              \
        int c_ = ac0 + q_;                                                        \
        int ar_ = c_ >> 2, akc_ = (c_ & 3) * 4;                                   \
        size_t ag_ = (size_t)(by * 128 + ar_) * K + k0_ + akc_;                   \
        cp16(sb_ + (ar_ * ASTRIDE + akc_) * 4, Ah + ag_);                         \
        cp16(sb_ + (A_SZ + ar_ * ASTRIDE + akc_) * 4, Al + ag_);                  \
        int br_ = c_ >> 5, bnc_ = (c_ & 31) * 4;                                  \
        size_t bg_ = (size_t)(k0_ + br_) * N + bx * 128 + bnc_;                   \
        cp16(sb_ + (2 * A_SZ + br_ * BSTRIDE + bnc_) * 4, Bh + bg_);              \
        cp16(sb_ + (2 * A_SZ + B_SZ + br_ * BSTRIDE + bnc_) * 4, Bl + bg_);       \
    }                                                                             \
    asm volatile("cp.async.commit_group;");                                       \
} while (0)

    const int nIter = K / 16;
    ISSUE(0, 0);
    int buf = 0;

    for (int it = 0; it < nIter; ++it) {
        if (it + 1 < nIter) {
            ISSUE(it + 1, buf ^ 1);
            asm volatile("cp.async.wait_group 1;");
        } else {
            asm volatile("cp.async.wait_group 0;");
        }
        __syncthreads();

        const uint32_t* sAh = smem_u + buf * STAGE_U32;
        const uint32_t* sAl = sAh + A_SZ;
        const uint32_t* sBh = sAh + 2 * A_SZ;
        const uint32_t* sBl = sBh + B_SZ;

#pragma unroll
        for (int ks = 0; ks < 16; ks += 8) {
            uint32_t ah[4][4], al[4][4];
#pragma unroll
            for (int mt = 0; mt < 4; ++mt) {
                int m0 = warp_m * 64 + mt * 16;
                const uint32_t* r0h = sAh + (m0 + lr) * ASTRIDE + ks + lc;
                const uint32_t* r1h = sAh + (m0 + lr + 8) * ASTRIDE + ks + lc;
                const uint32_t* r0l = sAl + (m0 + lr) * ASTRIDE + ks + lc;
                const uint32_t* r1l = sAl + (m0 + lr + 8) * ASTRIDE + ks + lc;
                ah[mt][0] = r0h[0]; ah[mt][1] = r1h[0];
                ah[mt][2] = r0h[4]; ah[mt][3] = r1h[4];
                al[mt][0] = r0l[0]; al[mt][1] = r1l[0];
                al[mt][2] = r0l[4]; al[mt][3] = r1l[4];
            }
            uint32_t bh[4][2], bl[4][2];
#pragma unroll
            for (int nt = 0; nt < 4; ++nt) {
                int n0 = warp_n * 32 + nt * 8;
                bh[nt][0] = sBh[(ks + lc) * BSTRIDE + n0 + lr];
                bh[nt][1] = sBh[(ks + lc + 4) * BSTRIDE + n0 + lr];
                bl[nt][0] = sBl[(ks + lc) * BSTRIDE + n0 + lr];
                bl[nt][1] = sBl[(ks + lc + 4) * BSTRIDE + n0 + lr];
            }
#pragma unroll
            for (int mt = 0; mt < 4; ++mt)
#pragma unroll
                for (int nt = 0; nt < 4; ++nt) {
                    mma_tf32(acc[mt][nt], ah[mt], bl[nt]);
                    mma_tf32(acc[mt][nt], al[mt], bh[nt]);
                    mma_tf32(acc[mt][nt], ah[mt], bh[nt]);
                }
        }
        __syncthreads();
        buf ^= 1;
    }

#pragma unroll
    for (int mt = 0; mt < 4; ++mt) {
        int row = by * 128 + warp_m * 64 + mt * 16 + lr;
#pragma unroll
        for (int nt = 0; nt < 4; ++nt) {
            int col = bx * 128 + warp_n * 32 + nt * 8 + lc * 2;
            float bv0 = 0.f, bv1 = 0.f;
            if (bias) { bv0 = bias[col]; bv1 = bias[col + 1]; }
            float2 r0 = make_float2(acc[mt][nt][0] + bv0, acc[mt][nt][1] + bv1);
            float2 r1 = make_float2(acc[mt][nt][2] + bv0, acc[mt][nt][3] + bv1);
            *(float2*)&C[(size_t)row * N + col] = r0;
            *(float2*)&C[(size_t)(row + 8) * N + col] = r1;
        }
    }
}

// ---------------------------------------------------------------------------
// RoPE (unchanged)
// ---------------------------------------------------------------------------
__global__ __launch_bounds__(256) void rope_kernel(const int* __restrict__ pos,
                                                   float* __restrict__ qkv)
{
    int idx = blockIdx.x * 256 + threadIdx.x;
    int j = idx & 63;
    int h = (idx >> 6) & 31;
    int t = idx >> 11;
    if (t >= T_SEQ) return;

    float inv_freq = expf(-13.815510557964274f * (float)j * (1.0f / 64.0f));
    float ang = (float)pos[t] * inv_freq;
    float s, c;
    sincosf(ang, &s, &c);

    size_t base;
    if (h < HQ) base = (size_t)t * QKV_N + (size_t)h * DH;
    else        base = (size_t)t * QKV_N + K_OFF + (size_t)(h - HQ) * DH;

    float x1 = qkv[base + j];
    float x2 = qkv[base + 64 + j];
    qkv[base + j]      = x1 * c - x2 * s;
    qkv[base + 64 + j] = x2 * c + x1 * s;
}

// ---------------------------------------------------------------------------
// Flash attention (unchanged from R5 baseline)
// ---------------------------------------------------------------------------
#define FBM 64
#define FBN 64
#define QS_PAD 68
#define FLASH_SMEM_FLOATS (128 * QS_PAD * 2 + FBN * DH + FBM * QS_PAD)
#define FLASH_SMEM_BYTES (FLASH_SMEM_FLOATS * 4)

__global__ __launch_bounds__(256) void flash_kernel(const float* __restrict__ qkv,
                                                    float* __restrict__ attn)
{
    extern __shared__ float sm[];
    float* Qs = sm;
    float* Ks = Qs + 128 * QS_PAD;
    float* Vs = Ks + 128 * QS_PAD;
    float* Ps = Vs + FBN * DH;

    const int qt = blockIdx.x;
    const int h = blockIdx.y;
    const int hkv = h / 7;
    const int tid = threadIdx.x;
    const int tx = tid & 15;
    const int ty = tid >> 4;
    const float scale = 0.08838834764831845f;

    for (int idx = tid; idx < FBM * 32; idx += 256) {
        int m = idx >> 5;
        int k4 = (idx & 31) << 2;
        float4 v = *(const float4*)&qkv[(size_t)(qt * FBM + m) * QKV_N + h * DH + k4];
        Qs[(k4 + 0) * QS_PAD + m] = v.x;
        Qs[(k4 + 1) * QS_PAD + m] = v.y;
        Qs[(k4 + 2) * QS_PAD + m] = v.z;
        Qs[(k4 + 3) * QS_PAD + m] = v.w;
    }

    float o[4][8];
    float mrow[4], lrow[4];
#pragma unroll
    for (int i = 0; i < 4; ++i) {
        mrow[i] = -1e30f;
        lrow[i] = 0.f;
#pragma unroll
        for (int d = 0; d < 8; ++d) o[i][d] = 0.f;
    }

    for (int kt = 0; kt <= qt; ++kt) {
        __syncthreads();
        for (int idx = tid; idx < FBN * 32; idx += 256) {
            int r = idx >> 5;
            int k4 = (idx & 31) << 2;
            size_t base = (size_t)(kt * FBN + r) * QKV_N;
            float4 kv = *(const float4*)&qkv[base + K_OFF + hkv * DH + k4];
            Ks[(k4 + 0) * QS_PAD + r] = kv.x;
            Ks[(k4 + 1) * QS_PAD + r] = kv.y;
            Ks[(k4 + 2) * QS_PAD + r] = kv.z;
            Ks[(k4 + 3) * QS_PAD + r] = kv.w;
            float4 vv = *(const float4*)&qkv[base + V_OFF + hkv * DH + k4];
            *(float4*)&Vs[r * DH + k4] = vv;
        }
        __syncthreads();

        float s[4][4];
#pragma unroll
        for (int i = 0; i < 4; ++i)
#pragma unroll
            for (int j = 0; j < 4; ++j) s[i][j] = 0.f;

        for (int k = 0; k < DH; ++k) {
            float4 a = *(const float4*)&Qs[k * QS_PAD + 4 * ty];
            float4 b = *(const float4*)&Ks[k * QS_PAD + 4 * tx];
            float av[4] = {a.x, a.y, a.z, a.w};
            float bv[4] = {b.x, b.y, b.z, b.w};
#pragma unroll
            for (int i = 0; i < 4; ++i)
#pragma unroll
                for (int j = 0; j < 4; ++j)
                    s[i][j] += av[i] * bv[j];
        }

        const bool diag = (kt == qt);
#pragma unroll
        for (int i = 0; i < 4; ++i)
#pragma unroll
            for (int j = 0; j < 4; ++j) {
                float v = s[i][j] * scale;
                if (diag && (4 * tx + j) > (4 * ty + i)) v = -1e30f;
                s[i][j] = v;
            }

#pragma unroll
        for (int i = 0; i < 4; ++i) {
            float mx = fmaxf(fmaxf(s[i][0], s[i][1]), fmaxf(s[i][2], s[i][3]));
#pragma unroll
            for (int off = 1; off < 16; off <<= 1)
                mx = fmaxf(mx, __shfl_xor_sync(0xffffffffu, mx, off));
            float mn = fmaxf(mrow[i], mx);
            float corr = __expf(mrow[i] - mn);
            mrow[i] = mn;
            float rs = 0.f;
#pragma unroll
            for (int j = 0; j < 4; ++j) {
                float p = __expf(s[i][j] - mn);
                s[i][j] = p;
                rs += p;
            }
#pragma unroll
            for (int off = 1; off < 16; off <<= 1)
                rs += __shfl_xor_sync(0xffffffffu, rs, off);
            lrow[i] = lrow[i] * corr + rs;
#pragma unroll
            for (int d = 0; d < 8; ++d) o[i][d] *= corr;
            *(float4*)&Ps[(4 * ty + i) * QS_PAD + 4 * tx] =
                make_float4(s[i][0], s[i][1], s[i][2], s[i][3]);
        }
        __syncthreads();

        for (int kp = 0; kp < FBN; ++kp) {
            float4 v0 = *(const float4*)&Vs[kp * DH + tx * 8];
            float4 v1 = *(const float4*)&Vs[kp * DH + tx * 8 + 4];
#pragma unroll
            for (int i = 0; i < 4; ++i) {
                float p = Ps[(4 * ty + i) * QS_PAD + kp];
                o[i][0] += p * v0.x;
                o[i][1] += p * v0.y;
                o[i][2] += p * v0.z;
                o[i][3] += p * v0.w;
                o[i][4] += p * v1.x;
                o[i][5] += p * v1.y;
                o[i][6] += p * v1.z;
                o[i][7] += p * v1.w;
            }
        }
    }

#pragma unroll
    for (int i = 0; i < 4; ++i) {
        float inv = 1.f / lrow[i];
        int row = qt * FBM + 4 * ty + i;
        float* op = attn + (size_t)row * D_MODEL + h * DH + tx * 8;
        float4 r0 = make_float4(o[i][0] * inv, o[i][1] * inv, o[i][2] * inv, o[i][3] * inv);
        float4 r1 = make_float4(o[i][4] * inv, o[i][5] * inv, o[i][6] * inv, o[i][7] * inv);
        *(float4*)(op) = r0;
        *(float4*)(op + 4) = r1;
    }
}

// ---------------------------------------------------------------------------
extern "C" void kernel_launch(void* const* d_in, const int* in_sizes, int n_in,
                              void* d_out, int out_size)
{
    const int* positions   = (const int*)d_in[0];
    const float* hidden    = (const float*)d_in[1];
    const float* Wqkv      = (const float*)d_in[2];
    const float* bqkv      = (const float*)d_in[3];
    const float* Wo        = (const float*)d_in[4];
    float* out = (float*)d_out;

    float *qkv, *attn;
    uint32_t *wqh, *wql, *woh, *wol, *hh, *hl, *ath, *atl;
    cudaGetSymbolAddress((void**)&qkv, g_qkv);
    cudaGetSymbolAddress((void**)&attn, g_attn);
    cudaGetSymbolAddress((void**)&wqh, g_Wqkv_h);
    cudaGetSymbolAddress((void**)&wql, g_Wqkv_l);
    cudaGetSymbolAddress((void**)&woh, g_Wo_h);
    cudaGetSymbolAddress((void**)&wol, g_Wo_l);
    cudaGetSymbolAddress((void**)&hh, g_hid_h);
    cudaGetSymbolAddress((void**)&hl, g_hid_l);
    cudaGetSymbolAddress((void**)&ath, g_att_h);
    cudaGetSymbolAddress((void**)&atl, g_att_l);

    cudaFuncSetAttribute(flash_kernel,
                         cudaFuncAttributeMaxDynamicSharedMemorySize,
                         FLASH_SMEM_BYTES);
    cudaFuncSetAttribute(tf32s_gemm_kernel,
                         cudaFuncAttributeMaxDynamicSharedMemorySize,
                         GEMM_SMEM_BYTES);

    // 0) pre-split inputs + weights into tf32 hi/lo
    split_kernel<<<(unsigned)(HID_ELEMS / 4 + 255) / 256, 256>>>(hidden, hh, hl, HID_ELEMS / 4);
    split_kernel<<<(unsigned)(W_QKV_ELEMS / 4 + 255) / 256, 256>>>(Wqkv, wqh, wql, W_QKV_ELEMS / 4);
    split_kernel<<<(unsigned)(W_O_ELEMS / 4 + 255) / 256, 256>>>(Wo, woh, wol, W_O_ELEMS / 4);

    // 1) QKV = hidden @ W_qkv + b
    tf32s_gemm_kernel<<<dim3(QKV_N / 128, T_SEQ / 128), 256, GEMM_SMEM_BYTES>>>(
        hh, hl, wqh, wql, bqkv, qkv, T_SEQ, QKV_N, D_MODEL);

    // 2) RoPE
    rope_kernel<<<(T_SEQ * 32 * 64) / 256, 256>>>(positions, qkv);

    // 3) Flash attention
    flash_kernel<<<dim3(T_SEQ / FBM, HQ), 256, FLASH_SMEM_BYTES>>>(qkv, attn);

    // 4) split attn, then out = attn @ W_o
    split_kernel<<<(unsigned)(HID_ELEMS / 4 + 255) / 256, 256>>>(attn, ath, atl, HID_ELEMS / 4);
    tf32s_gemm_kernel<<<dim3(D_MODEL / 128, T_SEQ / 128), 256, GEMM_SMEM_BYTES>>>(
        ath, atl, woh, wol, nullptr, out, T_SEQ, D_MODEL, D_MODEL);
}